// round 15
// baseline (speedup 1.0000x reference)
#include <cuda_runtime.h>
#include <math.h>

#define NN 46080
#define BBG 64
#define BLKG 720
#define EE 400000
#define CX 128
#define CE 32
#define SORTN 16384
#define HSH 16384
#define CTPAD 132
#define OFF_X 0
#define OFF_EIO 5898240
#define OFF_ATTR 6698240
#define OFF_BATCH 19498240
#define OFF_XG 19544320

typedef unsigned long long u64;
typedef unsigned int u32;

__device__ int g_rs[NN + 1];
__device__ int g_rev[EE];
__device__ float g_ns[NN * CE];
__device__ float g_ea[EE * CE];
__device__ double g_bnstat[2 * CE];
__device__ float g_bna[CE], g_bnd[CE];
__device__ float g_snr;
__device__ float g_u[EE];
__device__ float g_score[EE];
__device__ double g_gsum[BBG];
__device__ unsigned char g_sel[EE];
__device__ int g_xmask[NN];
__device__ int g_lab[NN];
__device__ int g_repcnt[BBG];
__device__ int g_comp[NN];
__device__ int g_bout[NN];
__device__ int g_mlist[NN];
__device__ int g_minv[NN];
__device__ int g_mcnt;
__device__ int g_rbtot;
__device__ float g_h[NN * CX];
__device__ float g_xc[NN * CX];
__device__ float g_pa[NN * CX];
__device__ float g_pb[NN * CX];
__device__ int g_has[NN];
__device__ float g_xg[BBG * CX];
__device__ u32 g_ukeys[BBG * SORTN];
__device__ int g_erank[EE];
__device__ int g_ucnt[BBG];
__device__ int g_ub[BBG + 1];

// ---------------- eio = -1 fill ----------------
__global__ void k_fill(float* out) {
    int i = blockIdx.x * blockDim.x + threadIdx.x;
    if (i < 2 * EE) out[OFF_EIO + i] = -1.f;
}

// ---------------- rowstart ----------------
__global__ void k_rowstart(const int* __restrict__ row) {
    int r = blockIdx.x * blockDim.x + threadIdx.x;
    if (r > NN) return;
    int lo = 0, hi = EE;
    while (lo < hi) { int m = (lo + hi) >> 1; if (row[m] < r) lo = m + 1; else hi = m; }
    g_rs[r] = lo;
}

// ---------------- reverse edge index ----------------
__global__ void k_rev(const int* __restrict__ row, const int* __restrict__ col) {
    int e = blockIdx.x * blockDim.x + threadIdx.x;
    if (e >= EE) return;
    int t = col[e], v = row[e];
    int lo = g_rs[t], hi = g_rs[t + 1];
    while (lo < hi) { int m = (lo + hi) >> 1; if (col[m] < v) lo = m + 1; else hi = m; }
    g_rev[e] = lo;
}

// ---------------- nodesum ----------------
__global__ void k_nodesum(const float* __restrict__ eattr) {
    int w = (blockIdx.x * blockDim.x + threadIdx.x) >> 5;
    int l = threadIdx.x & 31;
    if (w >= NN) return;
    float s = 0.f;
    for (int e = g_rs[w]; e < g_rs[w + 1]; e++) s += eattr[g_rev[e] * CE + l];
    g_ns[w * CE + l] = s;
}

// ---------------- slim linear (float4 Ws reads, 4.2KB smem) --------------------
__global__ void k_lin(const int* __restrict__ row, const float* __restrict__ eattr,
                      const float* __restrict__ We, const float* __restrict__ be) {
    __shared__ float Ws[CE * CE], bs[CE];
    int t = threadIdx.x;
    for (int i = t; i < CE * CE; i += 256) Ws[i] = We[i];
    if (t < CE) bs[t] = be[t];
    __syncthreads();
    int e = blockIdx.x * 256 + t;
    if (e >= EE) return;
    float in[CE], o[CE];
    int r = row[e];
    #pragma unroll
    for (int k = 0; k < CE; k += 4) {
        float4 a = *(const float4*)&g_ns[r * CE + k];
        float4 b = *(const float4*)&eattr[e * CE + k];
        in[k] = a.x + b.x; in[k+1] = a.y + b.y; in[k+2] = a.z + b.z; in[k+3] = a.w + b.w;
    }
    #pragma unroll
    for (int j = 0; j < CE; j++) o[j] = bs[j];
    #pragma unroll 8
    for (int k = 0; k < CE; k++) {
        float ik = in[k];
        #pragma unroll
        for (int j = 0; j < CE; j += 4) {
            float4 w = *(const float4*)&Ws[k * CE + j];
            o[j]   += ik * w.x; o[j+1] += ik * w.y;
            o[j+2] += ik * w.z; o[j+3] += ik * w.w;
        }
    }
    #pragma unroll
    for (int j = 0; j < CE; j += 4)
        *(float4*)&g_ea[e * CE + j] = make_float4(o[j], o[j+1], o[j+2], o[j+3]);
}

// ---------------- BN stats: block-reduced, 148 atomics/address -----------------
__global__ void k_bnstats() {
    __shared__ double dsum[8][33], dsq[8][33];
    int t = threadIdx.x;
    int l = t & 31, wp = t >> 5;
    int w = (blockIdx.x * 256 + t) >> 5;     // global warp id
    int nw = (gridDim.x * 256) >> 5;
    double s = 0.0, q = 0.0;
    for (int e = w; e < EE; e += nw) {
        float v = g_ea[e * CE + l];
        s += v; q += (double)v * v;
    }
    dsum[wp][l] = s; dsq[wp][l] = q;
    __syncthreads();
    if (t < CE) {
        double ss = 0.0, qq = 0.0;
        #pragma unroll
        for (int i = 0; i < 8; i++) { ss += dsum[i][t]; qq += dsq[i][t]; }
        atomicAdd(&g_bnstat[t], ss);
        atomicAdd(&g_bnstat[CE + t], qq);
    }
}

// ---------------- BN finalize + S norm ----------------
__global__ void k_bnfin(const float* __restrict__ g, const float* __restrict__ b,
                        const float* __restrict__ S) {
    int j = threadIdx.x;
    float v = S[j] * S[j];
    for (int o = 16; o; o >>= 1) v += __shfl_down_sync(~0u, v, o);
    if (j == 0) g_snr = sqrtf(v);
    double mu = g_bnstat[j] / (double)EE;
    double var = g_bnstat[CE + j] / (double)EE - mu * mu;
    float a = g[j] / (float)sqrt(var + 1e-5);
    g_bna[j] = a; g_bnd[j] = b[j] - (float)mu * a;
}

// ---------------- u[e] = dot(relu(bn(ea[e])), S), 8 edges per warp -------------
__global__ void k_uu(const float* __restrict__ S) {
    int w = (blockIdx.x * blockDim.x + threadIdx.x) >> 5;
    int l = threadIdx.x & 31;
    int e0 = w * 8;
    if (e0 >= EE) return;
    float ba = g_bna[l], bd = g_bnd[l], sl = S[l];
    #pragma unroll
    for (int j = 0; j < 8; j++) {
        int e = e0 + j;
        if (e >= EE) break;
        float v = fmaxf(g_ea[e * CE + l] * ba + bd, 0.f) * sl;
        for (int o = 16; o; o >>= 1) v += __shfl_down_sync(~0u, v, o);
        if (l == 0) g_u[e] = v;
    }
}

// ---------------- score + per-graph sums ----------------
__global__ void k_score2(const int* __restrict__ row) {
    __shared__ double sloc[2];
    int t = threadIdx.x;
    if (t < 2) sloc[t] = 0.0;
    __syncthreads();
    int e = blockIdx.x * 256 + t;
    int g0 = row[min(blockIdx.x * 256, EE - 1)] / BLKG;
    if (e < EE) {
        float z = g_u[e] + g_u[g_rev[e]];
        float s = 1.f / (1.f + expf(-z / g_snr));
        g_score[e] = s;
        int gg = row[e] / BLKG;
        atomicAdd(&sloc[gg == g0 ? 0 : 1], (double)s);
    }
    __syncthreads();
    if (t == 0) {
        atomicAdd(&g_gsum[g0], sloc[0]);
        int g1 = row[min(blockIdx.x * 256 + 255, EE - 1)] / BLKG;
        if (g1 != g0 && sloc[1] != 0.0) atomicAdd(&g_gsum[g1], sloc[1]);
    }
}

// ---------------- CC per graph, fused gmean + selection ----------------
__global__ void k_cc(const int* __restrict__ row, const int* __restrict__ col) {
    extern __shared__ u32 eb[];
    __shared__ int lab[BLKG];
    __shared__ int chg, rc, ecnt;
    int g = blockIdx.x, t = threadIdx.x;
    int base = g * BLKG;
    int e0 = g_rs[base], e1 = g_rs[base + BLKG];
    for (int i = t; i < BLKG; i += blockDim.x) lab[i] = i;
    if (t == 0) { chg = 1; rc = 0; ecnt = 0; }
    __syncthreads();
    int c = e1 - e0;
    float gm = c ? (float)(g_gsum[g] / (double)c) : 0.f;
    for (int e = e0 + t; e < e1; e += blockDim.x) {
        float s = g_score[e];
        unsigned char sl = (s <= 0.5f) && (s < gm);
        g_sel[e] = sl;
        if (sl) {
            g_xmask[row[e]] = 1;
            int p = atomicAdd(&ecnt, 1);
            eb[p] = ((u32)(row[e] - base) << 10) | (u32)(col[e] - base);
        }
    }
    __syncthreads();
    int ne = ecnt;
    for (int it = 0; it < 256 && chg; it++) {
        __syncthreads();
        if (t == 0) chg = 0;
        __syncthreads();
        for (int i = t; i < ne; i += blockDim.x) {
            u32 p = eb[i];
            int r = p >> 10, cc = p & 1023;
            int lr = lab[r], lc = lab[cc];
            if (lr < lc) { if (atomicMin(&lab[cc], lr) > lr) chg = 1; }
            else if (lc < lr) { if (atomicMin(&lab[r], lc) > lc) chg = 1; }
        }
        __syncthreads();
        for (int i = t; i < BLKG; i += blockDim.x) {
            int l = lab[i], ll = lab[l];
            if (ll < l) { lab[i] = ll; chg = 1; }
        }
        __syncthreads();
    }
    for (int i = t; i < BLKG; i += blockDim.x) {
        g_lab[base + i] = lab[i];
        if (lab[i] == i) atomicAdd(&rc, 1);
    }
    __syncthreads();
    if (t == 0) g_repcnt[g] = rc;
}

// ---------------- comp ids + masked-node compaction ----------------
__global__ void k_comp() {
    __shared__ int s[1024];
    __shared__ int pref[BBG];
    int g = blockIdx.x, t = threadIdx.x;
    int base = g * BLKG;
    if (t < BBG) pref[t] = g_repcnt[t];
    s[t] = (t < BLKG && g_lab[base + t] == t) ? 1 : 0;
    __syncthreads();
    if (t == 0) {
        int a = 0;
        for (int i = 0; i < BBG; i++) { int v = pref[i]; pref[i] = a; a += v; }
        if (g == 0) g_rbtot = a;
    }
    for (int off = 1; off < 1024; off <<= 1) {
        int v = (t >= off) ? s[t - off] : 0;
        __syncthreads(); s[t] += v; __syncthreads();
    }
    if (t < BLKG) {
        int n = base + t;
        int c = pref[g] + s[g_lab[base + t]] - 1;
        g_comp[n] = c;
        g_bout[c] = g;
        if (g_xmask[n]) {
            int idx = atomicAdd(&g_mcnt, 1);
            g_mlist[idx] = n;
            g_minv[n] = idx;
        }
    }
}

// ---------------- unique coalesce keys via smem hash ----------------
__global__ void k_unique(const int* __restrict__ row, const int* __restrict__ col) {
    extern __shared__ u32 sh[];
    u32* hkey  = sh;
    u32* hrank = sh + HSH;
    u32* ulist = sh + 2 * HSH;
    __shared__ int part[1024];
    int g = blockIdx.x, t = threadIdx.x;
    int e0 = g_rs[g * BLKG], e1 = g_rs[(g + 1) * BLKG];
    for (int i = t; i < HSH; i += 1024) hkey[i] = 0xFFFFFFFFu;
    __syncthreads();
    for (int e = e0 + t; e < e1; e += 1024) {
        if (g_sel[e]) continue;
        u32 key = (u32)g_comp[row[e]] * (u32)NN + (u32)g_comp[col[e]];
        u32 h = (key * 2654435761u) & (HSH - 1);
        while (true) {
            u32 old = atomicCAS(&hkey[h], 0xFFFFFFFFu, key);
            if (old == 0xFFFFFFFFu || old == key) break;
            h = (h + 1) & (HSH - 1);
        }
        g_erank[e] = (int)h;
    }
    __syncthreads();
    int i0 = t * 16, run = 0;
    for (int j = 0; j < 16; j++) run += (hkey[i0 + j] != 0xFFFFFFFFu);
    part[t] = run;
    __syncthreads();
    for (int off = 1; off < 1024; off <<= 1) {
        int v = (t >= off) ? part[t - off] : 0;
        __syncthreads(); part[t] += v; __syncthreads();
    }
    int base = t ? part[t - 1] : 0;
    int w = 0;
    for (int j = 0; j < 16; j++) {
        u32 k2 = hkey[i0 + j];
        if (k2 != 0xFFFFFFFFu) ulist[base + w++] = k2;
    }
    int U = part[1023];
    if (t == 0) g_ucnt[g] = U;
    __syncthreads();
    int P = 2; while (P < U) P <<= 1;
    for (int i = U + t; i < P; i += 1024) ulist[i] = 0xFFFFFFFFu;
    __syncthreads();
    for (u32 k = 2; k <= (u32)P; k <<= 1)
        for (u32 j = k >> 1; j; j >>= 1) {
            for (u32 i = t; i < (u32)P; i += 1024) {
                u32 ixj = i ^ j;
                if (ixj > i) {
                    u32 a = ulist[i], b = ulist[ixj];
                    bool up = ((i & k) == 0);
                    if ((a > b) == up) { ulist[i] = b; ulist[ixj] = a; }
                }
            }
            __syncthreads();
        }
    for (int p = t; p < U; p += 1024) {
        u32 key = ulist[p];
        u32 h = (key * 2654435761u) & (HSH - 1);
        while (hkey[h] != key) h = (h + 1) & (HSH - 1);
        hrank[h] = (u32)p;
        g_ukeys[g * SORTN + p] = key;
    }
    __syncthreads();
    for (int e = e0 + t; e < e1; e += 1024) {
        if (g_sel[e]) continue;
        g_erank[e] = (int)hrank[g_erank[e]];
    }
}

__global__ void k_uscan() {
    if (threadIdx.x == 0) {
        int a = 0;
        for (int g = 0; g < BBG; g++) { g_ub[g] = a; a += g_ucnt[g]; }
        g_ub[BBG] = a;
    }
}

// ---------------- EGIN message, MASKED nodes only -> compact g_h ---------------
__global__ void k_msg2(const float* __restrict__ x, const float* __restrict__ Wedge,
                       const float* __restrict__ eps, const int* __restrict__ col) {
    __shared__ float Ws[CE * CX];
    __shared__ float Ba[CE], Bd[CE];
    int t = threadIdx.x;
    for (int i = t; i < CE * CX; i += 256) Ws[i] = Wedge[i];
    if (t < CE) { Ba[t] = g_bna[t]; Bd[t] = g_bnd[t]; }
    __syncthreads();
    int i = (blockIdx.x * 256 + t) >> 5;
    int l = t & 31;
    if (i >= g_mcnt) return;
    int n = g_mlist[i];
    float4 agg = make_float4(0.f, 0.f, 0.f, 0.f);
    for (int e = g_rs[n]; e < g_rs[n + 1]; e++) {
        if (!g_sel[e]) continue;
        float sc = g_score[e];
        float4 m = make_float4(0.f, 0.f, 0.f, 0.f);
        #pragma unroll 8
        for (int k = 0; k < CE; k++) {
            float ek = fmaxf(__ldg(&g_ea[e * CE + k]) * Ba[k] + Bd[k], 0.f) * sc;
            float4 w = *(const float4*)&Ws[k * CX + l * 4];
            m.x += ek * w.x; m.y += ek * w.y; m.z += ek * w.z; m.w += ek * w.w;
        }
        const float4 xc = *(const float4*)&x[(size_t)col[e] * CX + l * 4];
        agg.x += fmaxf(m.x + xc.x, 0.f); agg.y += fmaxf(m.y + xc.y, 0.f);
        agg.z += fmaxf(m.z + xc.z, 0.f); agg.w += fmaxf(m.w + xc.w, 0.f);
    }
    float ep = 1.f + eps[0];
    const float4 xn = *(const float4*)&x[(size_t)n * CX + l * 4];
    float4 h = make_float4(ep * xn.x + agg.x, ep * xn.y + agg.y,
                           ep * xn.z + agg.z, ep * xn.w + agg.w);
    *(float4*)&g_h[(size_t)i * CX + l * 4] = h;
}

// ---------------- fused fp32 double GEMM on compacted masked rows --------------
__global__ void k_gemmF(const float* __restrict__ W1, const float* __restrict__ b1,
                        const float* __restrict__ W2, const float* __restrict__ b2) {
    if (blockIdx.x * 128 >= g_mcnt) return;
    extern __shared__ float sm[];
    float* Ct = sm;
    float* As = sm + 128 * CTPAD;
    float* Bs = As + 8 * 128;
    int t = threadIdx.x;
    int m0 = blockIdx.x * 128;
    int tx = t & 15, ty = t >> 4;
    int lm = t >> 1, lk = (t & 1) * 4;
    int bk = t >> 5, bn = (t & 31) * 4;
    float acc[8][8];
    #pragma unroll
    for (int i = 0; i < 8; i++)
        #pragma unroll
        for (int j = 0; j < 8; j++) acc[i][j] = 0.f;
    for (int k0 = 0; k0 < CX; k0 += 8) {
        float4 av = *(const float4*)&g_h[(size_t)(m0 + lm) * CX + k0 + lk];
        As[(lk + 0) * 128 + lm] = av.x; As[(lk + 1) * 128 + lm] = av.y;
        As[(lk + 2) * 128 + lm] = av.z; As[(lk + 3) * 128 + lm] = av.w;
        *(float4*)&Bs[bk * 128 + bn] = *(const float4*)&W1[(size_t)(k0 + bk) * CX + bn];
        __syncthreads();
        #pragma unroll
        for (int kk = 0; kk < 8; kk++) {
            float4 a0 = *(float4*)&As[kk * 128 + ty * 8];
            float4 a1 = *(float4*)&As[kk * 128 + ty * 8 + 4];
            float4 b0 = *(float4*)&Bs[kk * 128 + tx * 8];
            float4 b1v = *(float4*)&Bs[kk * 128 + tx * 8 + 4];
            float am[8] = {a0.x, a0.y, a0.z, a0.w, a1.x, a1.y, a1.z, a1.w};
            float bv[8] = {b0.x, b0.y, b0.z, b0.w, b1v.x, b1v.y, b1v.z, b1v.w};
            #pragma unroll
            for (int i = 0; i < 8; i++)
                #pragma unroll
                for (int j = 0; j < 8; j++) acc[i][j] += am[i] * bv[j];
        }
        __syncthreads();
    }
    #pragma unroll
    for (int i = 0; i < 8; i++) {
        #pragma unroll
        for (int j = 0; j < 8; j += 4) {
            float4 bb = *(const float4*)&b1[tx * 8 + j];
            float4 o = make_float4(fmaxf(acc[i][j] + bb.x, 0.f), fmaxf(acc[i][j+1] + bb.y, 0.f),
                                   fmaxf(acc[i][j+2] + bb.z, 0.f), fmaxf(acc[i][j+3] + bb.w, 0.f));
            *(float4*)&Ct[(ty * 8 + i) * CTPAD + tx * 8 + j] = o;
        }
    }
    __syncthreads();
    #pragma unroll
    for (int i = 0; i < 8; i++)
        #pragma unroll
        for (int j = 0; j < 8; j++) acc[i][j] = 0.f;
    for (int k0 = 0; k0 < CX; k0 += 8) {
        *(float4*)&Bs[bk * 128 + bn] = *(const float4*)&W2[(size_t)(k0 + bk) * CX + bn];
        __syncthreads();
        #pragma unroll
        for (int kk = 0; kk < 8; kk++) {
            float am[8];
            #pragma unroll
            for (int i = 0; i < 8; i++) am[i] = Ct[(ty * 8 + i) * CTPAD + k0 + kk];
            float4 b0 = *(float4*)&Bs[kk * 128 + tx * 8];
            float4 b1v = *(float4*)&Bs[kk * 128 + tx * 8 + 4];
            float bv[8] = {b0.x, b0.y, b0.z, b0.w, b1v.x, b1v.y, b1v.z, b1v.w};
            #pragma unroll
            for (int i = 0; i < 8; i++)
                #pragma unroll
                for (int j = 0; j < 8; j++) acc[i][j] += am[i] * bv[j];
        }
        __syncthreads();
    }
    #pragma unroll
    for (int i = 0; i < 8; i++) {
        int m = m0 + ty * 8 + i;
        #pragma unroll
        for (int j = 0; j < 8; j += 4) {
            float4 bb = *(const float4*)&b2[tx * 8 + j];
            *(float4*)&g_xc[(size_t)m * CX + tx * 8 + j] =
                make_float4(acc[i][j] + bb.x, acc[i][j+1] + bb.y,
                            acc[i][j+2] + bb.z, acc[i][j+3] + bb.w);
        }
    }
}

// ---------------- pooling ----------------
__global__ void k_pool(const float* __restrict__ x) {
    int i = blockIdx.x * blockDim.x + threadIdx.x;
    if (i >= NN * 32) return;
    int n = i >> 5, q = (i & 31) * 4;
    int c = g_comp[n];
    if (g_xmask[n]) {
        float4 v = *(const float4*)&g_xc[(size_t)g_minv[n] * CX + q];
        atomicAdd(&g_pa[(size_t)c * CX + q], v.x); atomicAdd(&g_pa[(size_t)c * CX + q + 1], v.y);
        atomicAdd(&g_pa[(size_t)c * CX + q + 2], v.z); atomicAdd(&g_pa[(size_t)c * CX + q + 3], v.w);
    } else {
        float4 v = *(const float4*)&x[(size_t)n * CX + q];
        atomicAdd(&g_pb[(size_t)c * CX + q], v.x); atomicAdd(&g_pb[(size_t)c * CX + q + 1], v.y);
        atomicAdd(&g_pb[(size_t)c * CX + q + 2], v.z); atomicAdd(&g_pb[(size_t)c * CX + q + 3], v.w);
        if ((i & 31) == 0) g_has[c] = 1;
    }
}

__global__ void k_xout(float* out) {
    int i = blockIdx.x * blockDim.x + threadIdx.x;
    if (i >= NN * 32) return;
    int cl = i >> 5, q = (i & 31) * 4;
    int h = g_has[cl];
    float4 a = *(float4*)&g_pa[(size_t)cl * CX + q];
    float4 b = *(float4*)&g_pb[(size_t)cl * CX + q];
    float4 o = h ? b : a;
    *(float4*)&out[OFF_X + (size_t)cl * CX + q] = o;
    if ((i & 31) == 0) out[OFF_BATCH + cl] = (float)g_bout[cl];
    if (cl < g_rbtot) {
        int bg = g_bout[cl];
        atomicAdd(&g_xg[bg * CX + q], o.x); atomicAdd(&g_xg[bg * CX + q + 1], o.y);
        atomicAdd(&g_xg[bg * CX + q + 2], o.z); atomicAdd(&g_xg[bg * CX + q + 3], o.w);
    }
}

__global__ void k_bnxg(const float* __restrict__ g, const float* __restrict__ b, float* out) {
    int c = threadIdx.x;
    if (c >= CX) return;
    double s = 0.0, q = 0.0;
    for (int i = 0; i < BBG; i++) { double v = g_xg[i * CX + c]; s += v; q += v * v; }
    double mu = s / BBG, var = q / BBG - mu * mu;
    float a = g[c] / (float)sqrt(var + 1e-5);
    float d = b[c] - (float)mu * a;
    for (int i = 0; i < BBG; i++) out[OFF_XG + i * CX + c] = g_xg[i * CX + c] * a + d;
}

// ---------------- emit edge_index_out ----------------
__global__ void k_eio(float* out) {
    int g = blockIdx.x, t = threadIdx.x;
    int U = g_ucnt[g], ub = g_ub[g];
    for (int p = t; p < U; p += 256) {
        u32 key = g_ukeys[g * SORTN + p];
        int seg = ub + p;
        out[OFF_EIO + seg] = (float)(key / (u32)NN);
        out[OFF_EIO + EE + seg] = (float)(key % (u32)NN);
    }
}

// ---------------- emit attr: lane=channel, warp walks 8 edges, run-reduce ------
__global__ void k_emit2(const int* __restrict__ row, float* out) {
    __shared__ float Ba[CE], Bd[CE];
    int t = threadIdx.x;
    if (t < CE) { Ba[t] = g_bna[t]; Bd[t] = g_bnd[t]; }
    __syncthreads();
    int wid = (blockIdx.x * 256 + t) >> 5;
    int l = t & 31;
    int e0 = wid * 8;
    float acc = 0.f;
    int cur = -1;
    for (int j = 0; j < 8; j++) {
        int e = e0 + j;
        if (e >= EE) break;
        if (g_sel[e]) continue;
        int g = row[e] / BLKG;
        int seg = g_ub[g] + g_erank[e];
        float v = fmaxf(g_ea[e * CE + l] * Ba[l] + Bd[l], 0.f) * g_score[e];
        if (seg != cur) {
            if (cur >= 0) atomicAdd(&out[OFF_ATTR + (size_t)cur * CE + l], acc);
            cur = seg; acc = 0.f;
        }
        acc += v;
    }
    if (cur >= 0) atomicAdd(&out[OFF_ATTR + (size_t)cur * CE + l], acc);
}

extern "C" void kernel_launch(void* const* d_in, const int* in_sizes, int n_in,
                              void* d_out, int out_size) {
    const float* x = (const float*)d_in[0];
    const int* ei = (const int*)d_in[1];
    const float* eattr = (const float*)d_in[2];
    const float* S = (const float*)d_in[4];
    const float* We = (const float*)d_in[5];
    const float* be = (const float*)d_in[6];
    const float* bn_e_g = (const float*)d_in[7];
    const float* bn_e_b = (const float*)d_in[8];
    const float* Wedge = (const float*)d_in[9];
    const float* eps = (const float*)d_in[10];
    const float* W1 = (const float*)d_in[11];
    const float* b1 = (const float*)d_in[12];
    const float* W2 = (const float*)d_in[13];
    const float* b2 = (const float*)d_in[14];
    const float* bn_g = (const float*)d_in[15];
    const float* bn_b = (const float*)d_in[16];
    float* out = (float*)d_out;
    const int* row = ei;
    const int* col = ei + EE;

    const int GEMM_SMEM = (128 * CTPAD + 16 * 128) * 4;
    cudaFuncSetAttribute(k_unique, cudaFuncAttributeMaxDynamicSharedMemorySize, 3 * HSH * 4);
    cudaFuncSetAttribute(k_cc, cudaFuncAttributeMaxDynamicSharedMemorySize, HSH * 4);
    cudaFuncSetAttribute(k_gemmF, cudaFuncAttributeMaxDynamicSharedMemorySize, GEMM_SMEM);

    void *pa, *pb, *xg, *bnstat, *gsum, *xmask, *has, *bout, *mcnt;
    cudaGetSymbolAddress(&pa, g_pa);
    cudaGetSymbolAddress(&pb, g_pb);
    cudaGetSymbolAddress(&xg, g_xg);
    cudaGetSymbolAddress(&bnstat, g_bnstat);
    cudaGetSymbolAddress(&gsum, g_gsum);
    cudaGetSymbolAddress(&xmask, g_xmask);
    cudaGetSymbolAddress(&has, g_has);
    cudaGetSymbolAddress(&bout, g_bout);
    cudaGetSymbolAddress(&mcnt, g_mcnt);
    cudaMemsetAsync(out + OFF_ATTR, 0, (size_t)EE * CE * 4);
    cudaMemsetAsync(pa, 0, (size_t)NN * CX * 4);
    cudaMemsetAsync(pb, 0, (size_t)NN * CX * 4);
    cudaMemsetAsync(xg, 0, (size_t)BBG * CX * 4);
    cudaMemsetAsync(bnstat, 0, 2 * CE * 8);
    cudaMemsetAsync(gsum, 0, BBG * 8);
    cudaMemsetAsync(xmask, 0, NN * 4);
    cudaMemsetAsync(has, 0, NN * 4);
    cudaMemsetAsync(bout, 0, NN * 4);
    cudaMemsetAsync(mcnt, 0, 4);

    // k_lin stays the 4th kernel launch -> ncu capture slot
    k_rowstart<<<(NN + 256) / 256, 256>>>(row);
    k_rev<<<(EE + 255) / 256, 256>>>(row, col);
    k_nodesum<<<(NN * 32 + 255) / 256, 256>>>(eattr);
    k_lin<<<(EE + 255) / 256, 256>>>(row, eattr, We, be);
    k_bnstats<<<148, 256>>>();
    k_fill<<<(2 * EE + 255) / 256, 256>>>(out);
    k_bnfin<<<1, 32>>>(bn_e_g, bn_e_b, S);
    k_uu<<<(EE / 8 * 32 + 255) / 256, 256>>>(S);
    k_score2<<<(EE + 255) / 256, 256>>>(row);
    k_cc<<<BBG, 768, HSH * 4>>>(row, col);
    k_comp<<<BBG, 1024>>>();
    k_unique<<<BBG, 1024, 3 * HSH * 4>>>(row, col);
    k_uscan<<<1, 32>>>();
    k_msg2<<<(NN * 32 + 255) / 256, 256>>>(x, Wedge, eps, col);
    k_gemmF<<<NN / 128, 256, GEMM_SMEM>>>(W1, b1, W2, b2);
    k_pool<<<(NN * 32 + 255) / 256, 256>>>(x);
    k_xout<<<(NN * 32 + 255) / 256, 256>>>(out);
    k_bnxg<<<1, 128>>>(bn_g, bn_b, out);
    k_eio<<<BBG, 256>>>(out);
    k_emit2<<<(EE / 8 * 32 + 255) / 256, 256>>>(row, out);
}

// round 16
// speedup vs baseline: 1.0995x; 1.0995x over previous
#include <cuda_runtime.h>
#include <math.h>

#define NN 46080
#define BBG 64
#define BLKG 720
#define EE 400000
#define CX 128
#define CE 32
#define SORTN 16384
#define HSH 16384
#define CTPAD 132
#define OFF_X 0
#define OFF_EIO 5898240
#define OFF_ATTR 6698240
#define OFF_BATCH 19498240
#define OFF_XG 19544320

typedef unsigned long long u64;
typedef unsigned int u32;

__device__ int g_rs[NN + 1];
__device__ int g_rev[EE];
__device__ float g_ns[NN * CE];
__device__ float g_ea[EE * CE];
__device__ double g_bnstat[2 * CE];
__device__ float g_bna[CE], g_bnd[CE];
__device__ float g_snr;
__device__ float g_u[EE];
__device__ float g_score[EE];
__device__ double g_gsum[BBG];
__device__ unsigned char g_sel[EE];
__device__ int g_xmask[NN];
__device__ int g_lab[NN];
__device__ int g_repcnt[BBG];
__device__ int g_comp[NN];
__device__ int g_bout[NN];
__device__ int g_mlist[NN];
__device__ int g_minv[NN];
__device__ int g_mcnt;
__device__ int g_rbtot;
__device__ float g_h[NN * CX];
__device__ float g_xc[NN * CX];
__device__ float g_pa[NN * CX];
__device__ float g_pb[NN * CX];
__device__ int g_has[NN];
__device__ float g_xg[BBG * CX];
__device__ u32 g_ukeys[BBG * SORTN];
__device__ int g_erank[EE];
__device__ int g_ucnt[BBG];
__device__ int g_ub[BBG + 1];

// ---------------- eio = -1 fill ----------------
__global__ void k_fill(float* out) {
    int i = blockIdx.x * blockDim.x + threadIdx.x;
    if (i < 2 * EE) out[OFF_EIO + i] = -1.f;
}

// ---------------- rowstart ----------------
__global__ void k_rowstart(const int* __restrict__ row) {
    int r = blockIdx.x * blockDim.x + threadIdx.x;
    if (r > NN) return;
    int lo = 0, hi = EE;
    while (lo < hi) { int m = (lo + hi) >> 1; if (row[m] < r) lo = m + 1; else hi = m; }
    g_rs[r] = lo;
}

// ---------------- reverse edge index ----------------
__global__ void k_rev(const int* __restrict__ row, const int* __restrict__ col) {
    int e = blockIdx.x * blockDim.x + threadIdx.x;
    if (e >= EE) return;
    int t = col[e], v = row[e];
    int lo = g_rs[t], hi = g_rs[t + 1];
    while (lo < hi) { int m = (lo + hi) >> 1; if (col[m] < v) lo = m + 1; else hi = m; }
    g_rev[e] = lo;
}

// ---------------- nodesum ----------------
__global__ void k_nodesum(const float* __restrict__ eattr) {
    int w = (blockIdx.x * blockDim.x + threadIdx.x) >> 5;
    int l = threadIdx.x & 31;
    if (w >= NN) return;
    float s = 0.f;
    for (int e = g_rs[w]; e < g_rs[w + 1]; e++) s += eattr[g_rev[e] * CE + l];
    g_ns[w * CE + l] = s;
}

// ---------------- linear + butterfly-fused BN stats (6.3KB smem) ---------------
__global__ void k_lin(const int* __restrict__ row, const float* __restrict__ eattr,
                      const float* __restrict__ We, const float* __restrict__ be) {
    __shared__ float Ws[CE * CE], bs[CE];
    __shared__ float wsu[8][33], wsq[8][33];
    int t = threadIdx.x;
    int lane = t & 31, wid = t >> 5;
    for (int i = t; i < CE * CE; i += 256) Ws[i] = We[i];
    if (t < CE) bs[t] = be[t];
    __syncthreads();
    int e = blockIdx.x * 256 + t;
    bool ok = (e < EE);
    float in[CE], o[CE];
    if (ok) {
        int r = row[e];
        #pragma unroll
        for (int k = 0; k < CE; k += 4) {
            float4 a = *(const float4*)&g_ns[r * CE + k];
            float4 b = *(const float4*)&eattr[e * CE + k];
            in[k] = a.x + b.x; in[k+1] = a.y + b.y; in[k+2] = a.z + b.z; in[k+3] = a.w + b.w;
        }
    } else {
        #pragma unroll
        for (int k = 0; k < CE; k++) in[k] = 0.f;
    }
    #pragma unroll
    for (int j = 0; j < CE; j++) o[j] = ok ? bs[j] : 0.f;
    #pragma unroll 8
    for (int k = 0; k < CE; k++) {
        float ik = in[k];
        #pragma unroll
        for (int j = 0; j < CE; j += 4) {
            float4 w = *(const float4*)&Ws[k * CE + j];
            o[j]   += ik * w.x; o[j+1] += ik * w.y;
            o[j+2] += ik * w.z; o[j+3] += ik * w.w;
        }
    }
    if (ok) {
        #pragma unroll
        for (int j = 0; j < CE; j += 4)
            *(float4*)&g_ea[e * CE + j] = make_float4(o[j], o[j+1], o[j+2], o[j+3]);
    }
    // butterfly reduction per 8-channel quarter: warp sums per channel
    #pragma unroll
    for (int q = 0; q < 4; q++) {
        float a[8], b[8];
        #pragma unroll
        for (int j = 0; j < 8; j++) { float v = o[q * 8 + j]; a[j] = v; b[j] = v * v; }
        #pragma unroll
        for (int k = 0; k < 3; k++) {
            int d = 1 << k;
            int half = 4 >> k;   // len 8 -> 4 -> 2 -> 1
            bool up = (lane & d) != 0;
            #pragma unroll
            for (int j = 0; j < 4; j++) {
                if (j >= half) break;
                float sA = up ? a[j] : a[j + half];
                float sB = up ? b[j] : b[j + half];
                float rA = __shfl_xor_sync(0xffffffffu, sA, d);
                float rB = __shfl_xor_sync(0xffffffffu, sB, d);
                a[j] = (up ? a[j + half] : a[j]) + rA;
                b[j] = (up ? b[j + half] : b[j]) + rB;
            }
        }
        a[0] += __shfl_xor_sync(0xffffffffu, a[0], 8);
        b[0] += __shfl_xor_sync(0xffffffffu, b[0], 8);
        a[0] += __shfl_xor_sync(0xffffffffu, a[0], 16);
        b[0] += __shfl_xor_sync(0xffffffffu, b[0], 16);
        if (lane < 8) {
            int ch = q * 8 + (((lane & 1) << 2) | (lane & 2) | ((lane >> 2) & 1));
            wsu[wid][ch] = a[0];
            wsq[wid][ch] = b[0];
        }
    }
    __syncthreads();
    if (t < CE) {
        double s = 0.0, q = 0.0;
        #pragma unroll
        for (int w = 0; w < 8; w++) { s += wsu[w][t]; q += wsq[w][t]; }
        atomicAdd(&g_bnstat[t], s);
        atomicAdd(&g_bnstat[CE + t], q);
    }
}

// ---------------- BN finalize + S norm ----------------
__global__ void k_bnfin(const float* __restrict__ g, const float* __restrict__ b,
                        const float* __restrict__ S) {
    int j = threadIdx.x;
    float v = S[j] * S[j];
    for (int o = 16; o; o >>= 1) v += __shfl_down_sync(~0u, v, o);
    if (j == 0) g_snr = sqrtf(v);
    double mu = g_bnstat[j] / (double)EE;
    double var = g_bnstat[CE + j] / (double)EE - mu * mu;
    float a = g[j] / (float)sqrt(var + 1e-5);
    g_bna[j] = a; g_bnd[j] = b[j] - (float)mu * a;
}

// ---------------- u[e] = dot(relu(bn(ea[e])), S), 8 edges per warp -------------
__global__ void k_uu(const float* __restrict__ S) {
    int w = (blockIdx.x * blockDim.x + threadIdx.x) >> 5;
    int l = threadIdx.x & 31;
    int e0 = w * 8;
    if (e0 >= EE) return;
    float ba = g_bna[l], bd = g_bnd[l], sl = S[l];
    #pragma unroll
    for (int j = 0; j < 8; j++) {
        int e = e0 + j;
        if (e >= EE) break;
        float v = fmaxf(g_ea[e * CE + l] * ba + bd, 0.f) * sl;
        for (int o = 16; o; o >>= 1) v += __shfl_down_sync(~0u, v, o);
        if (l == 0) g_u[e] = v;
    }
}

// ---------------- score + per-graph sums ----------------
__global__ void k_score2(const int* __restrict__ row) {
    __shared__ double sloc[2];
    int t = threadIdx.x;
    if (t < 2) sloc[t] = 0.0;
    __syncthreads();
    int e = blockIdx.x * 256 + t;
    int g0 = row[min(blockIdx.x * 256, EE - 1)] / BLKG;
    if (e < EE) {
        float z = g_u[e] + g_u[g_rev[e]];
        float s = 1.f / (1.f + expf(-z / g_snr));
        g_score[e] = s;
        int gg = row[e] / BLKG;
        atomicAdd(&sloc[gg == g0 ? 0 : 1], (double)s);
    }
    __syncthreads();
    if (t == 0) {
        atomicAdd(&g_gsum[g0], sloc[0]);
        int g1 = row[min(blockIdx.x * 256 + 255, EE - 1)] / BLKG;
        if (g1 != g0 && sloc[1] != 0.0) atomicAdd(&g_gsum[g1], sloc[1]);
    }
}

// ---------------- CC per graph, fused gmean + selection ----------------
__global__ void k_cc(const int* __restrict__ row, const int* __restrict__ col) {
    extern __shared__ u32 eb[];
    __shared__ int lab[BLKG];
    __shared__ int chg, rc, ecnt;
    int g = blockIdx.x, t = threadIdx.x;
    int base = g * BLKG;
    int e0 = g_rs[base], e1 = g_rs[base + BLKG];
    for (int i = t; i < BLKG; i += blockDim.x) lab[i] = i;
    if (t == 0) { chg = 1; rc = 0; ecnt = 0; }
    __syncthreads();
    int c = e1 - e0;
    float gm = c ? (float)(g_gsum[g] / (double)c) : 0.f;
    for (int e = e0 + t; e < e1; e += blockDim.x) {
        float s = g_score[e];
        unsigned char sl = (s <= 0.5f) && (s < gm);
        g_sel[e] = sl;
        if (sl) {
            g_xmask[row[e]] = 1;
            int p = atomicAdd(&ecnt, 1);
            eb[p] = ((u32)(row[e] - base) << 10) | (u32)(col[e] - base);
        }
    }
    __syncthreads();
    int ne = ecnt;
    for (int it = 0; it < 256 && chg; it++) {
        __syncthreads();
        if (t == 0) chg = 0;
        __syncthreads();
        for (int i = t; i < ne; i += blockDim.x) {
            u32 p = eb[i];
            int r = p >> 10, cc = p & 1023;
            int lr = lab[r], lc = lab[cc];
            if (lr < lc) { if (atomicMin(&lab[cc], lr) > lr) chg = 1; }
            else if (lc < lr) { if (atomicMin(&lab[r], lc) > lc) chg = 1; }
        }
        __syncthreads();
        for (int i = t; i < BLKG; i += blockDim.x) {
            int l = lab[i], ll = lab[l];
            if (ll < l) { lab[i] = ll; chg = 1; }
        }
        __syncthreads();
    }
    for (int i = t; i < BLKG; i += blockDim.x) {
        g_lab[base + i] = lab[i];
        if (lab[i] == i) atomicAdd(&rc, 1);
    }
    __syncthreads();
    if (t == 0) g_repcnt[g] = rc;
}

// ---------------- comp ids + masked-node compaction ----------------
__global__ void k_comp() {
    __shared__ int s[1024];
    __shared__ int pref[BBG];
    int g = blockIdx.x, t = threadIdx.x;
    int base = g * BLKG;
    if (t < BBG) pref[t] = g_repcnt[t];
    s[t] = (t < BLKG && g_lab[base + t] == t) ? 1 : 0;
    __syncthreads();
    if (t == 0) {
        int a = 0;
        for (int i = 0; i < BBG; i++) { int v = pref[i]; pref[i] = a; a += v; }
        if (g == 0) g_rbtot = a;
    }
    for (int off = 1; off < 1024; off <<= 1) {
        int v = (t >= off) ? s[t - off] : 0;
        __syncthreads(); s[t] += v; __syncthreads();
    }
    if (t < BLKG) {
        int n = base + t;
        int c = pref[g] + s[g_lab[base + t]] - 1;
        g_comp[n] = c;
        g_bout[c] = g;
        if (g_xmask[n]) {
            int idx = atomicAdd(&g_mcnt, 1);
            g_mlist[idx] = n;
            g_minv[n] = idx;
        }
    }
}

// ---------------- unique coalesce keys via smem hash ----------------
__global__ void k_unique(const int* __restrict__ row, const int* __restrict__ col) {
    extern __shared__ u32 sh[];
    u32* hkey  = sh;
    u32* hrank = sh + HSH;
    u32* ulist = sh + 2 * HSH;
    __shared__ int part[1024];
    int g = blockIdx.x, t = threadIdx.x;
    int e0 = g_rs[g * BLKG], e1 = g_rs[(g + 1) * BLKG];
    for (int i = t; i < HSH; i += 1024) hkey[i] = 0xFFFFFFFFu;
    __syncthreads();
    for (int e = e0 + t; e < e1; e += 1024) {
        if (g_sel[e]) continue;
        u32 key = (u32)g_comp[row[e]] * (u32)NN + (u32)g_comp[col[e]];
        u32 h = (key * 2654435761u) & (HSH - 1);
        while (true) {
            u32 old = atomicCAS(&hkey[h], 0xFFFFFFFFu, key);
            if (old == 0xFFFFFFFFu || old == key) break;
            h = (h + 1) & (HSH - 1);
        }
        g_erank[e] = (int)h;
    }
    __syncthreads();
    int i0 = t * 16, run = 0;
    for (int j = 0; j < 16; j++) run += (hkey[i0 + j] != 0xFFFFFFFFu);
    part[t] = run;
    __syncthreads();
    for (int off = 1; off < 1024; off <<= 1) {
        int v = (t >= off) ? part[t - off] : 0;
        __syncthreads(); part[t] += v; __syncthreads();
    }
    int base = t ? part[t - 1] : 0;
    int w = 0;
    for (int j = 0; j < 16; j++) {
        u32 k2 = hkey[i0 + j];
        if (k2 != 0xFFFFFFFFu) ulist[base + w++] = k2;
    }
    int U = part[1023];
    if (t == 0) g_ucnt[g] = U;
    __syncthreads();
    int P = 2; while (P < U) P <<= 1;
    for (int i = U + t; i < P; i += 1024) ulist[i] = 0xFFFFFFFFu;
    __syncthreads();
    for (u32 k = 2; k <= (u32)P; k <<= 1)
        for (u32 j = k >> 1; j; j >>= 1) {
            for (u32 i = t; i < (u32)P; i += 1024) {
                u32 ixj = i ^ j;
                if (ixj > i) {
                    u32 a = ulist[i], b = ulist[ixj];
                    bool up = ((i & k) == 0);
                    if ((a > b) == up) { ulist[i] = b; ulist[ixj] = a; }
                }
            }
            __syncthreads();
        }
    for (int p = t; p < U; p += 1024) {
        u32 key = ulist[p];
        u32 h = (key * 2654435761u) & (HSH - 1);
        while (hkey[h] != key) h = (h + 1) & (HSH - 1);
        hrank[h] = (u32)p;
        g_ukeys[g * SORTN + p] = key;
    }
    __syncthreads();
    for (int e = e0 + t; e < e1; e += 1024) {
        if (g_sel[e]) continue;
        g_erank[e] = (int)hrank[g_erank[e]];
    }
}

__global__ void k_uscan() {
    if (threadIdx.x == 0) {
        int a = 0;
        for (int g = 0; g < BBG; g++) { g_ub[g] = a; a += g_ucnt[g]; }
        g_ub[BBG] = a;
    }
}

// ---------------- EGIN message, MASKED nodes only -> compact g_h ---------------
__global__ void k_msg2(const float* __restrict__ x, const float* __restrict__ Wedge,
                       const float* __restrict__ eps, const int* __restrict__ col) {
    __shared__ float Ws[CE * CX];
    __shared__ float Ba[CE], Bd[CE];
    int t = threadIdx.x;
    for (int i = t; i < CE * CX; i += 256) Ws[i] = Wedge[i];
    if (t < CE) { Ba[t] = g_bna[t]; Bd[t] = g_bnd[t]; }
    __syncthreads();
    int i = (blockIdx.x * 256 + t) >> 5;
    int l = t & 31;
    if (i >= g_mcnt) return;
    int n = g_mlist[i];
    float4 agg = make_float4(0.f, 0.f, 0.f, 0.f);
    for (int e = g_rs[n]; e < g_rs[n + 1]; e++) {
        if (!g_sel[e]) continue;
        float sc = g_score[e];
        float4 m = make_float4(0.f, 0.f, 0.f, 0.f);
        #pragma unroll 8
        for (int k = 0; k < CE; k++) {
            float ek = fmaxf(__ldg(&g_ea[e * CE + k]) * Ba[k] + Bd[k], 0.f) * sc;
            float4 w = *(const float4*)&Ws[k * CX + l * 4];
            m.x += ek * w.x; m.y += ek * w.y; m.z += ek * w.z; m.w += ek * w.w;
        }
        const float4 xc = *(const float4*)&x[(size_t)col[e] * CX + l * 4];
        agg.x += fmaxf(m.x + xc.x, 0.f); agg.y += fmaxf(m.y + xc.y, 0.f);
        agg.z += fmaxf(m.z + xc.z, 0.f); agg.w += fmaxf(m.w + xc.w, 0.f);
    }
    float ep = 1.f + eps[0];
    const float4 xn = *(const float4*)&x[(size_t)n * CX + l * 4];
    float4 h = make_float4(ep * xn.x + agg.x, ep * xn.y + agg.y,
                           ep * xn.z + agg.z, ep * xn.w + agg.w);
    *(float4*)&g_h[(size_t)i * CX + l * 4] = h;
}

// ---------------- fused fp32 double GEMM on compacted masked rows --------------
__global__ void k_gemmF(const float* __restrict__ W1, const float* __restrict__ b1,
                        const float* __restrict__ W2, const float* __restrict__ b2) {
    if (blockIdx.x * 128 >= g_mcnt) return;
    extern __shared__ float sm[];
    float* Ct = sm;
    float* As = sm + 128 * CTPAD;
    float* Bs = As + 8 * 128;
    int t = threadIdx.x;
    int m0 = blockIdx.x * 128;
    int tx = t & 15, ty = t >> 4;
    int lm = t >> 1, lk = (t & 1) * 4;
    int bk = t >> 5, bn = (t & 31) * 4;
    float acc[8][8];
    #pragma unroll
    for (int i = 0; i < 8; i++)
        #pragma unroll
        for (int j = 0; j < 8; j++) acc[i][j] = 0.f;
    for (int k0 = 0; k0 < CX; k0 += 8) {
        float4 av = *(const float4*)&g_h[(size_t)(m0 + lm) * CX + k0 + lk];
        As[(lk + 0) * 128 + lm] = av.x; As[(lk + 1) * 128 + lm] = av.y;
        As[(lk + 2) * 128 + lm] = av.z; As[(lk + 3) * 128 + lm] = av.w;
        *(float4*)&Bs[bk * 128 + bn] = *(const float4*)&W1[(size_t)(k0 + bk) * CX + bn];
        __syncthreads();
        #pragma unroll
        for (int kk = 0; kk < 8; kk++) {
            float4 a0 = *(float4*)&As[kk * 128 + ty * 8];
            float4 a1 = *(float4*)&As[kk * 128 + ty * 8 + 4];
            float4 b0 = *(float4*)&Bs[kk * 128 + tx * 8];
            float4 b1v = *(float4*)&Bs[kk * 128 + tx * 8 + 4];
            float am[8] = {a0.x, a0.y, a0.z, a0.w, a1.x, a1.y, a1.z, a1.w};
            float bv[8] = {b0.x, b0.y, b0.z, b0.w, b1v.x, b1v.y, b1v.z, b1v.w};
            #pragma unroll
            for (int i = 0; i < 8; i++)
                #pragma unroll
                for (int j = 0; j < 8; j++) acc[i][j] += am[i] * bv[j];
        }
        __syncthreads();
    }
    #pragma unroll
    for (int i = 0; i < 8; i++) {
        #pragma unroll
        for (int j = 0; j < 8; j += 4) {
            float4 bb = *(const float4*)&b1[tx * 8 + j];
            float4 o = make_float4(fmaxf(acc[i][j] + bb.x, 0.f), fmaxf(acc[i][j+1] + bb.y, 0.f),
                                   fmaxf(acc[i][j+2] + bb.z, 0.f), fmaxf(acc[i][j+3] + bb.w, 0.f));
            *(float4*)&Ct[(ty * 8 + i) * CTPAD + tx * 8 + j] = o;
        }
    }
    __syncthreads();
    #pragma unroll
    for (int i = 0; i < 8; i++)
        #pragma unroll
        for (int j = 0; j < 8; j++) acc[i][j] = 0.f;
    for (int k0 = 0; k0 < CX; k0 += 8) {
        *(float4*)&Bs[bk * 128 + bn] = *(const float4*)&W2[(size_t)(k0 + bk) * CX + bn];
        __syncthreads();
        #pragma unroll
        for (int kk = 0; kk < 8; kk++) {
            float am[8];
            #pragma unroll
            for (int i = 0; i < 8; i++) am[i] = Ct[(ty * 8 + i) * CTPAD + k0 + kk];
            float4 b0 = *(float4*)&Bs[kk * 128 + tx * 8];
            float4 b1v = *(float4*)&Bs[kk * 128 + tx * 8 + 4];
            float bv[8] = {b0.x, b0.y, b0.z, b0.w, b1v.x, b1v.y, b1v.z, b1v.w};
            #pragma unroll
            for (int i = 0; i < 8; i++)
                #pragma unroll
                for (int j = 0; j < 8; j++) acc[i][j] += am[i] * bv[j];
        }
        __syncthreads();
    }
    #pragma unroll
    for (int i = 0; i < 8; i++) {
        int m = m0 + ty * 8 + i;
        #pragma unroll
        for (int j = 0; j < 8; j += 4) {
            float4 bb = *(const float4*)&b2[tx * 8 + j];
            *(float4*)&g_xc[(size_t)m * CX + tx * 8 + j] =
                make_float4(acc[i][j] + bb.x, acc[i][j+1] + bb.y,
                            acc[i][j+2] + bb.z, acc[i][j+3] + bb.w);
        }
    }
}

// ---------------- pooling ----------------
__global__ void k_pool(const float* __restrict__ x) {
    int i = blockIdx.x * blockDim.x + threadIdx.x;
    if (i >= NN * 32) return;
    int n = i >> 5, q = (i & 31) * 4;
    int c = g_comp[n];
    if (g_xmask[n]) {
        float4 v = *(const float4*)&g_xc[(size_t)g_minv[n] * CX + q];
        atomicAdd(&g_pa[(size_t)c * CX + q], v.x); atomicAdd(&g_pa[(size_t)c * CX + q + 1], v.y);
        atomicAdd(&g_pa[(size_t)c * CX + q + 2], v.z); atomicAdd(&g_pa[(size_t)c * CX + q + 3], v.w);
    } else {
        float4 v = *(const float4*)&x[(size_t)n * CX + q];
        atomicAdd(&g_pb[(size_t)c * CX + q], v.x); atomicAdd(&g_pb[(size_t)c * CX + q + 1], v.y);
        atomicAdd(&g_pb[(size_t)c * CX + q + 2], v.z); atomicAdd(&g_pb[(size_t)c * CX + q + 3], v.w);
        if ((i & 31) == 0) g_has[c] = 1;
    }
}

__global__ void k_xout(float* out) {
    int i = blockIdx.x * blockDim.x + threadIdx.x;
    if (i >= NN * 32) return;
    int cl = i >> 5, q = (i & 31) * 4;
    int h = g_has[cl];
    float4 a = *(float4*)&g_pa[(size_t)cl * CX + q];
    float4 b = *(float4*)&g_pb[(size_t)cl * CX + q];
    float4 o = h ? b : a;
    *(float4*)&out[OFF_X + (size_t)cl * CX + q] = o;
    if ((i & 31) == 0) out[OFF_BATCH + cl] = (float)g_bout[cl];
    if (cl < g_rbtot) {
        int bg = g_bout[cl];
        atomicAdd(&g_xg[bg * CX + q], o.x); atomicAdd(&g_xg[bg * CX + q + 1], o.y);
        atomicAdd(&g_xg[bg * CX + q + 2], o.z); atomicAdd(&g_xg[bg * CX + q + 3], o.w);
    }
}

__global__ void k_bnxg(const float* __restrict__ g, const float* __restrict__ b, float* out) {
    int c = threadIdx.x;
    if (c >= CX) return;
    double s = 0.0, q = 0.0;
    for (int i = 0; i < BBG; i++) { double v = g_xg[i * CX + c]; s += v; q += v * v; }
    double mu = s / BBG, var = q / BBG - mu * mu;
    float a = g[c] / (float)sqrt(var + 1e-5);
    float d = b[c] - (float)mu * a;
    for (int i = 0; i < BBG; i++) out[OFF_XG + i * CX + c] = g_xg[i * CX + c] * a + d;
}

// ---------------- emit edge_index_out ----------------
__global__ void k_eio(float* out) {
    int g = blockIdx.x, t = threadIdx.x;
    int U = g_ucnt[g], ub = g_ub[g];
    for (int p = t; p < U; p += 256) {
        u32 key = g_ukeys[g * SORTN + p];
        int seg = ub + p;
        out[OFF_EIO + seg] = (float)(key / (u32)NN);
        out[OFF_EIO + EE + seg] = (float)(key % (u32)NN);
    }
}

// ---------------- emit attr: lane=channel, warp walks 8 edges, run-reduce ------
__global__ void k_emit2(const int* __restrict__ row, float* out) {
    __shared__ float Ba[CE], Bd[CE];
    int t = threadIdx.x;
    if (t < CE) { Ba[t] = g_bna[t]; Bd[t] = g_bnd[t]; }
    __syncthreads();
    int wid = (blockIdx.x * 256 + t) >> 5;
    int l = t & 31;
    int e0 = wid * 8;
    float acc = 0.f;
    int cur = -1;
    for (int j = 0; j < 8; j++) {
        int e = e0 + j;
        if (e >= EE) break;
        if (g_sel[e]) continue;
        int g = row[e] / BLKG;
        int seg = g_ub[g] + g_erank[e];
        float v = fmaxf(g_ea[e * CE + l] * Ba[l] + Bd[l], 0.f) * g_score[e];
        if (seg != cur) {
            if (cur >= 0) atomicAdd(&out[OFF_ATTR + (size_t)cur * CE + l], acc);
            cur = seg; acc = 0.f;
        }
        acc += v;
    }
    if (cur >= 0) atomicAdd(&out[OFF_ATTR + (size_t)cur * CE + l], acc);
}

extern "C" void kernel_launch(void* const* d_in, const int* in_sizes, int n_in,
                              void* d_out, int out_size) {
    const float* x = (const float*)d_in[0];
    const int* ei = (const int*)d_in[1];
    const float* eattr = (const float*)d_in[2];
    const float* S = (const float*)d_in[4];
    const float* We = (const float*)d_in[5];
    const float* be = (const float*)d_in[6];
    const float* bn_e_g = (const float*)d_in[7];
    const float* bn_e_b = (const float*)d_in[8];
    const float* Wedge = (const float*)d_in[9];
    const float* eps = (const float*)d_in[10];
    const float* W1 = (const float*)d_in[11];
    const float* b1 = (const float*)d_in[12];
    const float* W2 = (const float*)d_in[13];
    const float* b2 = (const float*)d_in[14];
    const float* bn_g = (const float*)d_in[15];
    const float* bn_b = (const float*)d_in[16];
    float* out = (float*)d_out;
    const int* row = ei;
    const int* col = ei + EE;

    const int GEMM_SMEM = (128 * CTPAD + 16 * 128) * 4;
    cudaFuncSetAttribute(k_unique, cudaFuncAttributeMaxDynamicSharedMemorySize, 3 * HSH * 4);
    cudaFuncSetAttribute(k_cc, cudaFuncAttributeMaxDynamicSharedMemorySize, HSH * 4);
    cudaFuncSetAttribute(k_gemmF, cudaFuncAttributeMaxDynamicSharedMemorySize, GEMM_SMEM);

    void *pa, *pb, *xg, *bnstat, *gsum, *xmask, *has, *bout, *mcnt;
    cudaGetSymbolAddress(&pa, g_pa);
    cudaGetSymbolAddress(&pb, g_pb);
    cudaGetSymbolAddress(&xg, g_xg);
    cudaGetSymbolAddress(&bnstat, g_bnstat);
    cudaGetSymbolAddress(&gsum, g_gsum);
    cudaGetSymbolAddress(&xmask, g_xmask);
    cudaGetSymbolAddress(&has, g_has);
    cudaGetSymbolAddress(&bout, g_bout);
    cudaGetSymbolAddress(&mcnt, g_mcnt);
    cudaMemsetAsync(out + OFF_ATTR, 0, (size_t)EE * CE * 4);
    cudaMemsetAsync(pa, 0, (size_t)NN * CX * 4);
    cudaMemsetAsync(pb, 0, (size_t)NN * CX * 4);
    cudaMemsetAsync(xg, 0, (size_t)BBG * CX * 4);
    cudaMemsetAsync(bnstat, 0, 2 * CE * 8);
    cudaMemsetAsync(gsum, 0, BBG * 8);
    cudaMemsetAsync(xmask, 0, NN * 4);
    cudaMemsetAsync(has, 0, NN * 4);
    cudaMemsetAsync(bout, 0, NN * 4);
    cudaMemsetAsync(mcnt, 0, 4);

    // k_lin stays the 4th kernel launch -> ncu capture slot
    k_rowstart<<<(NN + 256) / 256, 256>>>(row);
    k_rev<<<(EE + 255) / 256, 256>>>(row, col);
    k_nodesum<<<(NN * 32 + 255) / 256, 256>>>(eattr);
    k_lin<<<(EE + 255) / 256, 256>>>(row, eattr, We, be);
    k_fill<<<(2 * EE + 255) / 256, 256>>>(out);
    k_bnfin<<<1, 32>>>(bn_e_g, bn_e_b, S);
    k_uu<<<(EE / 8 * 32 + 255) / 256, 256>>>(S);
    k_score2<<<(EE + 255) / 256, 256>>>(row);
    k_cc<<<BBG, 768, HSH * 4>>>(row, col);
    k_comp<<<BBG, 1024>>>();
    k_unique<<<BBG, 1024, 3 * HSH * 4>>>(row, col);
    k_uscan<<<1, 32>>>();
    k_msg2<<<(NN * 32 + 255) / 256, 256>>>(x, Wedge, eps, col);
    k_gemmF<<<NN / 128, 256, GEMM_SMEM>>>(W1, b1, W2, b2);
    k_pool<<<(NN * 32 + 255) / 256, 256>>>(x);
    k_xout<<<(NN * 32 + 255) / 256, 256>>>(out);
    k_bnxg<<<1, 128>>>(bn_g, bn_b, out);
    k_eio<<<BBG, 256>>>(out);
    k_emit2<<<(EE / 8 * 32 + 255) / 256, 256>>>(row, out);
}

// round 17
// speedup vs baseline: 1.1230x; 1.0214x over previous
#include <cuda_runtime.h>
#include <math.h>

#define NN 46080
#define BBG 64
#define BLKG 720
#define EE 400000
#define CX 128
#define CE 32
#define SORTN 16384
#define HSH 16384
#define CTPAD 132
#define OFF_X 0
#define OFF_EIO 5898240
#define OFF_ATTR 6698240
#define OFF_BATCH 19498240
#define OFF_XG 19544320

typedef unsigned long long u64;
typedef unsigned int u32;

__device__ int g_rs[NN + 1];
__device__ int g_rev[EE];
__device__ float g_ns[NN * CE];
__device__ float g_ea[EE * CE];
__device__ float g_bna[CE], g_bnd[CE];
__device__ float g_snr;
__device__ float g_u[EE];
__device__ float g_score[EE];
__device__ unsigned char g_sel[EE];
__device__ int g_lab[NN];
__device__ int g_repcnt[BBG];
__device__ int g_comp[NN];
__device__ int g_mlist[NN];
__device__ int g_minv[NN];
__device__ int g_rbtot;
__device__ float g_h[NN * CX];
__device__ float g_xc[NN * CX];
__device__ u32 g_ukeys[BBG * SORTN];
__device__ int g_erank[EE];
__device__ int g_ucnt[BBG];
__device__ int g_ub[BBG + 1];

// consolidated zero-init pools
__device__ float  g_fz[2 * NN * CX + BBG * CX];     // pa | pb | xg
__device__ int    g_iz[3 * NN + 1];                 // xmask | has | bout | mcnt
__device__ double g_dz[2 * CE + BBG];               // bnstat | gsum

#define g_pa     (g_fz)
#define g_pb     (g_fz + NN * CX)
#define g_xg     (g_fz + 2 * NN * CX)
#define g_xmask  (g_iz)
#define g_has    (g_iz + NN)
#define g_bout   (g_iz + 2 * NN)
#define g_mcnt   (g_iz[3 * NN])
#define g_bnstat (g_dz)
#define g_gsum   (g_dz + 2 * CE)

// ---------------- eio = -1 fill ----------------
__global__ void k_fill(float* out) {
    int i = blockIdx.x * blockDim.x + threadIdx.x;
    if (i < 2 * EE) out[OFF_EIO + i] = -1.f;
}

// ---------------- rowstart ----------------
__global__ void k_rowstart(const int* __restrict__ row) {
    int r = blockIdx.x * blockDim.x + threadIdx.x;
    if (r > NN) return;
    int lo = 0, hi = EE;
    while (lo < hi) { int m = (lo + hi) >> 1; if (row[m] < r) lo = m + 1; else hi = m; }
    g_rs[r] = lo;
}

// ---------------- reverse edge index ----------------
__global__ void k_rev(const int* __restrict__ row, const int* __restrict__ col) {
    int e = blockIdx.x * blockDim.x + threadIdx.x;
    if (e >= EE) return;
    int t = col[e], v = row[e];
    int lo = g_rs[t], hi = g_rs[t + 1];
    while (lo < hi) { int m = (lo + hi) >> 1; if (col[m] < v) lo = m + 1; else hi = m; }
    g_rev[e] = lo;
}

// ---------------- nodesum ----------------
__global__ void k_nodesum(const float* __restrict__ eattr) {
    int w = (blockIdx.x * blockDim.x + threadIdx.x) >> 5;
    int l = threadIdx.x & 31;
    if (w >= NN) return;
    float s = 0.f;
    for (int e = g_rs[w]; e < g_rs[w + 1]; e++) s += eattr[g_rev[e] * CE + l];
    g_ns[w * CE + l] = s;
}

// ---------------- linear + butterfly-fused BN stats (occ-boosted) --------------
__global__ void __launch_bounds__(256, 4)
k_lin(const int* __restrict__ row, const float* __restrict__ eattr,
      const float* __restrict__ We, const float* __restrict__ be) {
    __shared__ float Ws[CE * CE], bs[CE];
    __shared__ float wsu[8][33], wsq[8][33];
    int t = threadIdx.x;
    int lane = t & 31, wid = t >> 5;
    for (int i = t; i < CE * CE; i += 256) Ws[i] = We[i];
    if (t < CE) bs[t] = be[t];
    __syncthreads();
    int e = blockIdx.x * 256 + t;
    bool ok = (e < EE);
    float in[CE], o[CE];
    if (ok) {
        int r = row[e];
        #pragma unroll
        for (int k = 0; k < CE; k += 4) {
            float4 a = *(const float4*)&g_ns[r * CE + k];
            float4 b = *(const float4*)&eattr[e * CE + k];
            in[k] = a.x + b.x; in[k+1] = a.y + b.y; in[k+2] = a.z + b.z; in[k+3] = a.w + b.w;
        }
    } else {
        #pragma unroll
        for (int k = 0; k < CE; k++) in[k] = 0.f;
    }
    #pragma unroll
    for (int j = 0; j < CE; j++) o[j] = ok ? bs[j] : 0.f;
    #pragma unroll 8
    for (int k = 0; k < CE; k++) {
        float ik = in[k];
        #pragma unroll
        for (int j = 0; j < CE; j += 4) {
            float4 w = *(const float4*)&Ws[k * CE + j];
            o[j]   += ik * w.x; o[j+1] += ik * w.y;
            o[j+2] += ik * w.z; o[j+3] += ik * w.w;
        }
    }
    if (ok) {
        #pragma unroll
        for (int j = 0; j < CE; j += 4)
            *(float4*)&g_ea[e * CE + j] = make_float4(o[j], o[j+1], o[j+2], o[j+3]);
    }
    #pragma unroll
    for (int q = 0; q < 4; q++) {
        float a[8], b[8];
        #pragma unroll
        for (int j = 0; j < 8; j++) { float v = o[q * 8 + j]; a[j] = v; b[j] = v * v; }
        #pragma unroll
        for (int k = 0; k < 3; k++) {
            int d = 1 << k;
            int half = 4 >> k;
            bool up = (lane & d) != 0;
            #pragma unroll
            for (int j = 0; j < 4; j++) {
                if (j >= half) break;
                float sA = up ? a[j] : a[j + half];
                float sB = up ? b[j] : b[j + half];
                float rA = __shfl_xor_sync(0xffffffffu, sA, d);
                float rB = __shfl_xor_sync(0xffffffffu, sB, d);
                a[j] = (up ? a[j + half] : a[j]) + rA;
                b[j] = (up ? b[j + half] : b[j]) + rB;
            }
        }
        a[0] += __shfl_xor_sync(0xffffffffu, a[0], 8);
        b[0] += __shfl_xor_sync(0xffffffffu, b[0], 8);
        a[0] += __shfl_xor_sync(0xffffffffu, a[0], 16);
        b[0] += __shfl_xor_sync(0xffffffffu, b[0], 16);
        if (lane < 8) {
            int ch = q * 8 + (((lane & 1) << 2) | (lane & 2) | ((lane >> 2) & 1));
            wsu[wid][ch] = a[0];
            wsq[wid][ch] = b[0];
        }
    }
    __syncthreads();
    if (t < CE) {
        double s = 0.0, q = 0.0;
        #pragma unroll
        for (int w = 0; w < 8; w++) { s += wsu[w][t]; q += wsq[w][t]; }
        atomicAdd(&g_bnstat[t], s);
        atomicAdd(&g_bnstat[CE + t], q);
    }
}

// ---------------- BN finalize + S norm ----------------
__global__ void k_bnfin(const float* __restrict__ g, const float* __restrict__ b,
                        const float* __restrict__ S) {
    int j = threadIdx.x;
    float v = S[j] * S[j];
    for (int o = 16; o; o >>= 1) v += __shfl_down_sync(~0u, v, o);
    if (j == 0) g_snr = sqrtf(v);
    double mu = g_bnstat[j] / (double)EE;
    double var = g_bnstat[CE + j] / (double)EE - mu * mu;
    float a = g[j] / (float)sqrt(var + 1e-5);
    g_bna[j] = a; g_bnd[j] = b[j] - (float)mu * a;
}

// ---------------- u[e] = dot(relu(bn(ea[e])), S), 8 edges per warp -------------
__global__ void k_uu(const float* __restrict__ S) {
    int w = (blockIdx.x * blockDim.x + threadIdx.x) >> 5;
    int l = threadIdx.x & 31;
    int e0 = w * 8;
    if (e0 >= EE) return;
    float ba = g_bna[l], bd = g_bnd[l], sl = S[l];
    #pragma unroll
    for (int j = 0; j < 8; j++) {
        int e = e0 + j;
        if (e >= EE) break;
        float v = fmaxf(g_ea[e * CE + l] * ba + bd, 0.f) * sl;
        for (int o = 16; o; o >>= 1) v += __shfl_down_sync(~0u, v, o);
        if (l == 0) g_u[e] = v;
    }
}

// ---------------- score + per-graph sums ----------------
__global__ void k_score2(const int* __restrict__ row) {
    __shared__ double sloc[2];
    int t = threadIdx.x;
    if (t < 2) sloc[t] = 0.0;
    __syncthreads();
    int e = blockIdx.x * 256 + t;
    int g0 = row[min(blockIdx.x * 256, EE - 1)] / BLKG;
    if (e < EE) {
        float z = g_u[e] + g_u[g_rev[e]];
        float s = 1.f / (1.f + expf(-z / g_snr));
        g_score[e] = s;
        int gg = row[e] / BLKG;
        atomicAdd(&sloc[gg == g0 ? 0 : 1], (double)s);
    }
    __syncthreads();
    if (t == 0) {
        atomicAdd(&g_gsum[g0], sloc[0]);
        int g1 = row[min(blockIdx.x * 256 + 255, EE - 1)] / BLKG;
        if (g1 != g0 && sloc[1] != 0.0) atomicAdd(&g_gsum[g1], sloc[1]);
    }
}

// ---------------- CC per graph, fused gmean + selection ----------------
__global__ void k_cc(const int* __restrict__ row, const int* __restrict__ col) {
    extern __shared__ u32 eb[];
    __shared__ int lab[BLKG];
    __shared__ int chg, rc, ecnt;
    int g = blockIdx.x, t = threadIdx.x;
    int base = g * BLKG;
    int e0 = g_rs[base], e1 = g_rs[base + BLKG];
    for (int i = t; i < BLKG; i += blockDim.x) lab[i] = i;
    if (t == 0) { chg = 1; rc = 0; ecnt = 0; }
    __syncthreads();
    int c = e1 - e0;
    float gm = c ? (float)(g_gsum[g] / (double)c) : 0.f;
    for (int e = e0 + t; e < e1; e += blockDim.x) {
        float s = g_score[e];
        unsigned char sl = (s <= 0.5f) && (s < gm);
        g_sel[e] = sl;
        if (sl) {
            g_xmask[row[e]] = 1;
            int p = atomicAdd(&ecnt, 1);
            eb[p] = ((u32)(row[e] - base) << 10) | (u32)(col[e] - base);
        }
    }
    __syncthreads();
    int ne = ecnt;
    for (int it = 0; it < 256 && chg; it++) {
        __syncthreads();
        if (t == 0) chg = 0;
        __syncthreads();
        for (int i = t; i < ne; i += blockDim.x) {
            u32 p = eb[i];
            int r = p >> 10, cc = p & 1023;
            int lr = lab[r], lc = lab[cc];
            if (lr < lc) { if (atomicMin(&lab[cc], lr) > lr) chg = 1; }
            else if (lc < lr) { if (atomicMin(&lab[r], lc) > lc) chg = 1; }
        }
        __syncthreads();
        for (int i = t; i < BLKG; i += blockDim.x) {
            int l = lab[i], ll = lab[l];
            if (ll < l) { lab[i] = ll; chg = 1; }
        }
        __syncthreads();
    }
    for (int i = t; i < BLKG; i += blockDim.x) {
        g_lab[base + i] = lab[i];
        if (lab[i] == i) atomicAdd(&rc, 1);
    }
    __syncthreads();
    if (t == 0) g_repcnt[g] = rc;
}

// ---------------- comp ids + masked-node compaction ----------------
__global__ void k_comp() {
    __shared__ int s[1024];
    __shared__ int pref[BBG];
    int g = blockIdx.x, t = threadIdx.x;
    int base = g * BLKG;
    if (t < BBG) pref[t] = g_repcnt[t];
    s[t] = (t < BLKG && g_lab[base + t] == t) ? 1 : 0;
    __syncthreads();
    if (t == 0) {
        int a = 0;
        for (int i = 0; i < BBG; i++) { int v = pref[i]; pref[i] = a; a += v; }
        if (g == 0) g_rbtot = a;
    }
    for (int off = 1; off < 1024; off <<= 1) {
        int v = (t >= off) ? s[t - off] : 0;
        __syncthreads(); s[t] += v; __syncthreads();
    }
    if (t < BLKG) {
        int n = base + t;
        int c = pref[g] + s[g_lab[base + t]] - 1;
        g_comp[n] = c;
        g_bout[c] = g;
        if (g_xmask[n]) {
            int idx = atomicAdd(&g_mcnt, 1);
            g_mlist[idx] = n;
            g_minv[n] = idx;
        }
    }
}

// ---------------- unique coalesce keys via smem hash ----------------
__global__ void k_unique(const int* __restrict__ row, const int* __restrict__ col) {
    extern __shared__ u32 sh[];
    u32* hkey  = sh;
    u32* hrank = sh + HSH;
    u32* ulist = sh + 2 * HSH;
    __shared__ int part[1024];
    int g = blockIdx.x, t = threadIdx.x;
    int e0 = g_rs[g * BLKG], e1 = g_rs[(g + 1) * BLKG];
    for (int i = t; i < HSH; i += 1024) hkey[i] = 0xFFFFFFFFu;
    __syncthreads();
    for (int e = e0 + t; e < e1; e += 1024) {
        if (g_sel[e]) continue;
        u32 key = (u32)g_comp[row[e]] * (u32)NN + (u32)g_comp[col[e]];
        u32 h = (key * 2654435761u) & (HSH - 1);
        while (true) {
            u32 old = atomicCAS(&hkey[h], 0xFFFFFFFFu, key);
            if (old == 0xFFFFFFFFu || old == key) break;
            h = (h + 1) & (HSH - 1);
        }
        g_erank[e] = (int)h;
    }
    __syncthreads();
    int i0 = t * 16, run = 0;
    for (int j = 0; j < 16; j++) run += (hkey[i0 + j] != 0xFFFFFFFFu);
    part[t] = run;
    __syncthreads();
    for (int off = 1; off < 1024; off <<= 1) {
        int v = (t >= off) ? part[t - off] : 0;
        __syncthreads(); part[t] += v; __syncthreads();
    }
    int base = t ? part[t - 1] : 0;
    int w = 0;
    for (int j = 0; j < 16; j++) {
        u32 k2 = hkey[i0 + j];
        if (k2 != 0xFFFFFFFFu) ulist[base + w++] = k2;
    }
    int U = part[1023];
    if (t == 0) g_ucnt[g] = U;
    __syncthreads();
    int P = 2; while (P < U) P <<= 1;
    for (int i = U + t; i < P; i += 1024) ulist[i] = 0xFFFFFFFFu;
    __syncthreads();
    for (u32 k = 2; k <= (u32)P; k <<= 1)
        for (u32 j = k >> 1; j; j >>= 1) {
            for (u32 i = t; i < (u32)P; i += 1024) {
                u32 ixj = i ^ j;
                if (ixj > i) {
                    u32 a = ulist[i], b = ulist[ixj];
                    bool up = ((i & k) == 0);
                    if ((a > b) == up) { ulist[i] = b; ulist[ixj] = a; }
                }
            }
            __syncthreads();
        }
    for (int p = t; p < U; p += 1024) {
        u32 key = ulist[p];
        u32 h = (key * 2654435761u) & (HSH - 1);
        while (hkey[h] != key) h = (h + 1) & (HSH - 1);
        hrank[h] = (u32)p;
        g_ukeys[g * SORTN + p] = key;
    }
    __syncthreads();
    for (int e = e0 + t; e < e1; e += 1024) {
        if (g_sel[e]) continue;
        g_erank[e] = (int)hrank[g_erank[e]];
    }
}

__global__ void k_uscan() {
    if (threadIdx.x == 0) {
        int a = 0;
        for (int g = 0; g < BBG; g++) { g_ub[g] = a; a += g_ucnt[g]; }
        g_ub[BBG] = a;
    }
}

// ---------------- EGIN message, MASKED nodes only -> compact g_h ---------------
__global__ void k_msg2(const float* __restrict__ x, const float* __restrict__ Wedge,
                       const float* __restrict__ eps, const int* __restrict__ col) {
    __shared__ float Ws[CE * CX];
    __shared__ float Ba[CE], Bd[CE];
    int t = threadIdx.x;
    for (int i = t; i < CE * CX; i += 256) Ws[i] = Wedge[i];
    if (t < CE) { Ba[t] = g_bna[t]; Bd[t] = g_bnd[t]; }
    __syncthreads();
    int i = (blockIdx.x * 256 + t) >> 5;
    int l = t & 31;
    if (i >= g_mcnt) return;
    int n = g_mlist[i];
    float4 agg = make_float4(0.f, 0.f, 0.f, 0.f);
    for (int e = g_rs[n]; e < g_rs[n + 1]; e++) {
        if (!g_sel[e]) continue;
        float sc = g_score[e];
        float4 m = make_float4(0.f, 0.f, 0.f, 0.f);
        #pragma unroll 8
        for (int k = 0; k < CE; k++) {
            float ek = fmaxf(__ldg(&g_ea[e * CE + k]) * Ba[k] + Bd[k], 0.f) * sc;
            float4 w = *(const float4*)&Ws[k * CX + l * 4];
            m.x += ek * w.x; m.y += ek * w.y; m.z += ek * w.z; m.w += ek * w.w;
        }
        const float4 xc = *(const float4*)&x[(size_t)col[e] * CX + l * 4];
        agg.x += fmaxf(m.x + xc.x, 0.f); agg.y += fmaxf(m.y + xc.y, 0.f);
        agg.z += fmaxf(m.z + xc.z, 0.f); agg.w += fmaxf(m.w + xc.w, 0.f);
    }
    float ep = 1.f + eps[0];
    const float4 xn = *(const float4*)&x[(size_t)n * CX + l * 4];
    float4 h = make_float4(ep * xn.x + agg.x, ep * xn.y + agg.y,
                           ep * xn.z + agg.z, ep * xn.w + agg.w);
    *(float4*)&g_h[(size_t)i * CX + l * 4] = h;
}

// ---------------- fused fp32 double GEMM on compacted masked rows --------------
__global__ void k_gemmF(const float* __restrict__ W1, const float* __restrict__ b1,
                        const float* __restrict__ W2, const float* __restrict__ b2) {
    if (blockIdx.x * 128 >= g_mcnt) return;
    extern __shared__ float sm[];
    float* Ct = sm;
    float* As = sm + 128 * CTPAD;
    float* Bs = As + 8 * 128;
    int t = threadIdx.x;
    int m0 = blockIdx.x * 128;
    int tx = t & 15, ty = t >> 4;
    int lm = t >> 1, lk = (t & 1) * 4;
    int bk = t >> 5, bn = (t & 31) * 4;
    float acc[8][8];
    #pragma unroll
    for (int i = 0; i < 8; i++)
        #pragma unroll
        for (int j = 0; j < 8; j++) acc[i][j] = 0.f;
    for (int k0 = 0; k0 < CX; k0 += 8) {
        float4 av = *(const float4*)&g_h[(size_t)(m0 + lm) * CX + k0 + lk];
        As[(lk + 0) * 128 + lm] = av.x; As[(lk + 1) * 128 + lm] = av.y;
        As[(lk + 2) * 128 + lm] = av.z; As[(lk + 3) * 128 + lm] = av.w;
        *(float4*)&Bs[bk * 128 + bn] = *(const float4*)&W1[(size_t)(k0 + bk) * CX + bn];
        __syncthreads();
        #pragma unroll
        for (int kk = 0; kk < 8; kk++) {
            float4 a0 = *(float4*)&As[kk * 128 + ty * 8];
            float4 a1 = *(float4*)&As[kk * 128 + ty * 8 + 4];
            float4 b0 = *(float4*)&Bs[kk * 128 + tx * 8];
            float4 b1v = *(float4*)&Bs[kk * 128 + tx * 8 + 4];
            float am[8] = {a0.x, a0.y, a0.z, a0.w, a1.x, a1.y, a1.z, a1.w};
            float bv[8] = {b0.x, b0.y, b0.z, b0.w, b1v.x, b1v.y, b1v.z, b1v.w};
            #pragma unroll
            for (int i = 0; i < 8; i++)
                #pragma unroll
                for (int j = 0; j < 8; j++) acc[i][j] += am[i] * bv[j];
        }
        __syncthreads();
    }
    #pragma unroll
    for (int i = 0; i < 8; i++) {
        #pragma unroll
        for (int j = 0; j < 8; j += 4) {
            float4 bb = *(const float4*)&b1[tx * 8 + j];
            float4 o = make_float4(fmaxf(acc[i][j] + bb.x, 0.f), fmaxf(acc[i][j+1] + bb.y, 0.f),
                                   fmaxf(acc[i][j+2] + bb.z, 0.f), fmaxf(acc[i][j+3] + bb.w, 0.f));
            *(float4*)&Ct[(ty * 8 + i) * CTPAD + tx * 8 + j] = o;
        }
    }
    __syncthreads();
    #pragma unroll
    for (int i = 0; i < 8; i++)
        #pragma unroll
        for (int j = 0; j < 8; j++) acc[i][j] = 0.f;
    for (int k0 = 0; k0 < CX; k0 += 8) {
        *(float4*)&Bs[bk * 128 + bn] = *(const float4*)&W2[(size_t)(k0 + bk) * CX + bn];
        __syncthreads();
        #pragma unroll
        for (int kk = 0; kk < 8; kk++) {
            float am[8];
            #pragma unroll
            for (int i = 0; i < 8; i++) am[i] = Ct[(ty * 8 + i) * CTPAD + k0 + kk];
            float4 b0 = *(float4*)&Bs[kk * 128 + tx * 8];
            float4 b1v = *(float4*)&Bs[kk * 128 + tx * 8 + 4];
            float bv[8] = {b0.x, b0.y, b0.z, b0.w, b1v.x, b1v.y, b1v.z, b1v.w};
            #pragma unroll
            for (int i = 0; i < 8; i++)
                #pragma unroll
                for (int j = 0; j < 8; j++) acc[i][j] += am[i] * bv[j];
        }
        __syncthreads();
    }
    #pragma unroll
    for (int i = 0; i < 8; i++) {
        int m = m0 + ty * 8 + i;
        #pragma unroll
        for (int j = 0; j < 8; j += 4) {
            float4 bb = *(const float4*)&b2[tx * 8 + j];
            *(float4*)&g_xc[(size_t)m * CX + tx * 8 + j] =
                make_float4(acc[i][j] + bb.x, acc[i][j+1] + bb.y,
                            acc[i][j+2] + bb.z, acc[i][j+3] + bb.w);
        }
    }
}

// ---------------- pooling ----------------
__global__ void k_pool(const float* __restrict__ x) {
    int i = blockIdx.x * blockDim.x + threadIdx.x;
    if (i >= NN * 32) return;
    int n = i >> 5, q = (i & 31) * 4;
    int c = g_comp[n];
    if (g_xmask[n]) {
        float4 v = *(const float4*)&g_xc[(size_t)g_minv[n] * CX + q];
        atomicAdd(&g_pa[(size_t)c * CX + q], v.x); atomicAdd(&g_pa[(size_t)c * CX + q + 1], v.y);
        atomicAdd(&g_pa[(size_t)c * CX + q + 2], v.z); atomicAdd(&g_pa[(size_t)c * CX + q + 3], v.w);
    } else {
        float4 v = *(const float4*)&x[(size_t)n * CX + q];
        atomicAdd(&g_pb[(size_t)c * CX + q], v.x); atomicAdd(&g_pb[(size_t)c * CX + q + 1], v.y);
        atomicAdd(&g_pb[(size_t)c * CX + q + 2], v.z); atomicAdd(&g_pb[(size_t)c * CX + q + 3], v.w);
        if ((i & 31) == 0) g_has[c] = 1;
    }
}

__global__ void k_xout(float* out) {
    int i = blockIdx.x * blockDim.x + threadIdx.x;
    if (i >= NN * 32) return;
    int cl = i >> 5, q = (i & 31) * 4;
    int h = g_has[cl];
    float4 a = *(float4*)&g_pa[(size_t)cl * CX + q];
    float4 b = *(float4*)&g_pb[(size_t)cl * CX + q];
    float4 o = h ? b : a;
    *(float4*)&out[OFF_X + (size_t)cl * CX + q] = o;
    if ((i & 31) == 0) out[OFF_BATCH + cl] = (float)g_bout[cl];
    if (cl < g_rbtot) {
        int bg = g_bout[cl];
        atomicAdd(&g_xg[bg * CX + q], o.x); atomicAdd(&g_xg[bg * CX + q + 1], o.y);
        atomicAdd(&g_xg[bg * CX + q + 2], o.z); atomicAdd(&g_xg[bg * CX + q + 3], o.w);
    }
}

__global__ void k_bnxg(const float* __restrict__ g, const float* __restrict__ b, float* out) {
    int c = threadIdx.x;
    if (c >= CX) return;
    double s = 0.0, q = 0.0;
    for (int i = 0; i < BBG; i++) { double v = g_xg[i * CX + c]; s += v; q += v * v; }
    double mu = s / BBG, var = q / BBG - mu * mu;
    float a = g[c] / (float)sqrt(var + 1e-5);
    float d = b[c] - (float)mu * a;
    for (int i = 0; i < BBG; i++) out[OFF_XG + i * CX + c] = g_xg[i * CX + c] * a + d;
}

// ---------------- emit edge_index_out ----------------
__global__ void k_eio(float* out) {
    int g = blockIdx.x, t = threadIdx.x;
    int U = g_ucnt[g], ub = g_ub[g];
    for (int p = t; p < U; p += 256) {
        u32 key = g_ukeys[g * SORTN + p];
        int seg = ub + p;
        out[OFF_EIO + seg] = (float)(key / (u32)NN);
        out[OFF_EIO + EE + seg] = (float)(key % (u32)NN);
    }
}

// ---------------- emit attr: lane=channel, warp walks 8 edges, run-reduce ------
__global__ void k_emit2(const int* __restrict__ row, float* out) {
    __shared__ float Ba[CE], Bd[CE];
    int t = threadIdx.x;
    if (t < CE) { Ba[t] = g_bna[t]; Bd[t] = g_bnd[t]; }
    __syncthreads();
    int wid = (blockIdx.x * 256 + t) >> 5;
    int l = t & 31;
    int e0 = wid * 8;
    float acc = 0.f;
    int cur = -1;
    for (int j = 0; j < 8; j++) {
        int e = e0 + j;
        if (e >= EE) break;
        if (g_sel[e]) continue;
        int g = row[e] / BLKG;
        int seg = g_ub[g] + g_erank[e];
        float v = fmaxf(g_ea[e * CE + l] * Ba[l] + Bd[l], 0.f) * g_score[e];
        if (seg != cur) {
            if (cur >= 0) atomicAdd(&out[OFF_ATTR + (size_t)cur * CE + l], acc);
            cur = seg; acc = 0.f;
        }
        acc += v;
    }
    if (cur >= 0) atomicAdd(&out[OFF_ATTR + (size_t)cur * CE + l], acc);
}

extern "C" void kernel_launch(void* const* d_in, const int* in_sizes, int n_in,
                              void* d_out, int out_size) {
    const float* x = (const float*)d_in[0];
    const int* ei = (const int*)d_in[1];
    const float* eattr = (const float*)d_in[2];
    const float* S = (const float*)d_in[4];
    const float* We = (const float*)d_in[5];
    const float* be = (const float*)d_in[6];
    const float* bn_e_g = (const float*)d_in[7];
    const float* bn_e_b = (const float*)d_in[8];
    const float* Wedge = (const float*)d_in[9];
    const float* eps = (const float*)d_in[10];
    const float* W1 = (const float*)d_in[11];
    const float* b1 = (const float*)d_in[12];
    const float* W2 = (const float*)d_in[13];
    const float* b2 = (const float*)d_in[14];
    const float* bn_g = (const float*)d_in[15];
    const float* bn_b = (const float*)d_in[16];
    float* out = (float*)d_out;
    const int* row = ei;
    const int* col = ei + EE;

    const int GEMM_SMEM = (128 * CTPAD + 16 * 128) * 4;
    cudaFuncSetAttribute(k_unique, cudaFuncAttributeMaxDynamicSharedMemorySize, 3 * HSH * 4);
    cudaFuncSetAttribute(k_cc, cudaFuncAttributeMaxDynamicSharedMemorySize, HSH * 4);
    cudaFuncSetAttribute(k_gemmF, cudaFuncAttributeMaxDynamicSharedMemorySize, GEMM_SMEM);

    void *fz, *iz, *dz;
    cudaGetSymbolAddress(&fz, g_fz);
    cudaGetSymbolAddress(&iz, g_iz);
    cudaGetSymbolAddress(&dz, g_dz);
    cudaMemsetAsync(out + OFF_ATTR, 0, (size_t)EE * CE * 4);
    cudaMemsetAsync(fz, 0, sizeof(float) * (2 * (size_t)NN * CX + BBG * CX));
    cudaMemsetAsync(iz, 0, sizeof(int) * (3 * NN + 1));
    cudaMemsetAsync(dz, 0, sizeof(double) * (2 * CE + BBG));

    // k_lin stays the 4th kernel launch -> ncu capture slot
    k_rowstart<<<(NN + 256) / 256, 256>>>(row);
    k_rev<<<(EE + 255) / 256, 256>>>(row, col);
    k_nodesum<<<(NN * 32 + 255) / 256, 256>>>(eattr);
    k_lin<<<(EE + 255) / 256, 256>>>(row, eattr, We, be);
    k_fill<<<(2 * EE + 255) / 256, 256>>>(out);
    k_bnfin<<<1, 32>>>(bn_e_g, bn_e_b, S);
    k_uu<<<(EE / 8 * 32 + 255) / 256, 256>>>(S);
    k_score2<<<(EE + 255) / 256, 256>>>(row);
    k_cc<<<BBG, 768, HSH * 4>>>(row, col);
    k_comp<<<BBG, 1024>>>();
    k_unique<<<BBG, 1024, 3 * HSH * 4>>>(row, col);
    k_uscan<<<1, 32>>>();
    k_msg2<<<(NN * 32 + 255) / 256, 256>>>(x, Wedge, eps, col);
    k_gemmF<<<NN / 128, 256, GEMM_SMEM>>>(W1, b1, W2, b2);
    k_pool<<<(NN * 32 + 255) / 256, 256>>>(x);
    k_xout<<<(NN * 32 + 255) / 256, 256>>>(out);
    k_bnxg<<<1, 128>>>(bn_g, bn_b, out);
    k_eio<<<BBG, 256>>>(out);
    k_emit2<<<(EE / 8 * 32 + 255) / 256, 256>>>(row, out);
}